// round 3
// baseline (speedup 1.0000x reference)
#include <cuda_runtime.h>
#include <math.h>

// ---------------- problem constants ----------------
#define BQ   8
#define LQ   128
#define TSEQ 384          // 3 * L tokens per batch
#define MTOK 3072         // BQ * TSEQ
#define DM   256          // d_model
#define DI   512          // d_inner
#define DS   16           // d_state
#define RK   16           // dt_rank
#define NL   4

// ---------------- scratch ----------------
__device__ float g_u   [MTOK * DM];
__device__ float g_res [MTOK * DM];
__device__ float g_rs2 [MTOK];          // per-row sum of squares (for rmsnorm)
__device__ float g_xz  [MTOK * 2 * DI];
__device__ float g_xc  [MTOK * DI];
__device__ float g_proj[MTOK * 48];
__device__ float g_y   [MTOK * DI];

// ---------------- embeddings + interleave -> u ; zero rs2 ----------------
__global__ void k_embed(const float* __restrict__ states,
                        const float* __restrict__ actions,
                        const float* __restrict__ goal,
                        const int*   __restrict__ timesteps,
                        const float* __restrict__ te_W,
                        const float* __restrict__ se_W, const float* __restrict__ se_b,
                        const float* __restrict__ ge_W, const float* __restrict__ ge_b,
                        const float* __restrict__ ae_W, const float* __restrict__ ae_b)
{
    int m = blockIdx.x;          // token 0..3071
    int e = threadIdx.x;         // 0..255
    if (e == 0) g_rs2[m] = 0.f;  // zero sumsq for bb_in epilogue
    int b = m / TSEQ, t = m % TSEQ;
    int slot = t % 3, l = t / 3;

    const float *inp, *Wm, *bi; int dim;
    if (slot == 0)      { inp = goal;    Wm = ge_W; bi = ge_b; dim = 6; }
    else if (slot == 1) { inp = states;  Wm = se_W; bi = se_b; dim = 6; }
    else                { inp = actions; Wm = ae_W; bi = ae_b; dim = 3; }

    float v = bi[e];
    const float* ip = inp + (size_t)(b * LQ + l) * dim;
    #pragma unroll 6
    for (int i = 0; i < dim; i++) v += ip[i] * Wm[i * DM + e];

    int ts = timesteps[b * LQ + l];
    v += te_W[(size_t)ts * DM + e];
    g_u[(size_t)m * DM + e] = v;
}

// ---------------- in_proj: 128x64 tile, rmsnorm folded into A-load ----------------
// C[3072,1024] = (res * rsqrt(rs2/256+eps) * nw) @ W[256,1024]
__global__ __launch_bounds__(256)
void k_inproj(const float* __restrict__ A,
              const float* __restrict__ W,
              const float* __restrict__ nw,
              float* __restrict__ C)
{
    __shared__ float As[16][128];
    __shared__ float Ws[16][68];

    int tid = threadIdx.x;
    int bm = blockIdx.y * 128, bn = blockIdx.x * 64;
    int tx = tid & 15;        // col group
    int ty = tid >> 4;        // row group (8 rows)
    int arow = tid >> 2;      // 0..63
    int acol = (tid & 3) * 4; // 0,4,8,12
    int wn = tx * 4;          // W col within tile; wk = ty

    float s0 = rsqrtf(g_rs2[bm + arow]      * (1.f / DM) + 1e-5f);
    float s1 = rsqrtf(g_rs2[bm + arow + 64] * (1.f / DM) + 1e-5f);

    const float* Ap0 = A + (size_t)(bm + arow) * DM + acol;
    const float* Ap1 = Ap0 + (size_t)64 * DM;

    float4 pa0 = *(const float4*)(Ap0);
    float4 pa1 = *(const float4*)(Ap1);
    float4 pw  = *(const float4*)(W + (size_t)ty * 1024 + bn + wn);

    float acc[8][4] = {};

    for (int k0 = 0; k0 < DM; k0 += 16) {
        __syncthreads();
        float n0 = nw[k0 + acol + 0], n1 = nw[k0 + acol + 1];
        float n2 = nw[k0 + acol + 2], n3 = nw[k0 + acol + 3];
        As[acol + 0][arow] = pa0.x * s0 * n0;
        As[acol + 1][arow] = pa0.y * s0 * n1;
        As[acol + 2][arow] = pa0.z * s0 * n2;
        As[acol + 3][arow] = pa0.w * s0 * n3;
        As[acol + 0][arow + 64] = pa1.x * s1 * n0;
        As[acol + 1][arow + 64] = pa1.y * s1 * n1;
        As[acol + 2][arow + 64] = pa1.z * s1 * n2;
        As[acol + 3][arow + 64] = pa1.w * s1 * n3;
        *(float4*)&Ws[ty][wn] = pw;
        __syncthreads();

        if (k0 + 16 < DM) {
            pa0 = *(const float4*)(Ap0 + k0 + 16);
            pa1 = *(const float4*)(Ap1 + k0 + 16);
            pw  = *(const float4*)(W + (size_t)(k0 + 16 + ty) * 1024 + bn + wn);
        }

        #pragma unroll
        for (int k = 0; k < 16; k++) {
            float4 a0 = *(const float4*)&As[k][ty * 8];
            float4 a1 = *(const float4*)&As[k][ty * 8 + 4];
            float4 w0 = *(const float4*)&Ws[k][tx * 4];
            float a[8] = {a0.x, a0.y, a0.z, a0.w, a1.x, a1.y, a1.z, a1.w};
            float w[4] = {w0.x, w0.y, w0.z, w0.w};
            #pragma unroll
            for (int i = 0; i < 8; i++)
                #pragma unroll
                for (int j = 0; j < 4; j++) acc[i][j] += a[i] * w[j];
        }
    }

    #pragma unroll
    for (int i = 0; i < 8; i++) {
        int row = bm + ty * 8 + i;
        #pragma unroll
        for (int j = 0; j < 4; j++)
            C[(size_t)row * 1024 + bn + tx * 4 + j] = acc[i][j];
    }
}

// ---------------- 64x64 SGEMM with split-K support + fused epilogues ----------------
// EPI 0: store acc(+bias) and atomic row-sumsq into g_rs2        (bb_in)
// EPI 1: C += acc, atomic row-sumsq into g_rs2                   (out_proj)
// EPI 2: atomicAdd(C, acc) for split-K, cols guarded by N        (xproj)
template<int EPI>
__global__ __launch_bounds__(256)
void k_gemm64(const float* __restrict__ A, int lda,
              const float* __restrict__ W, int N, int Ks,
              const float* __restrict__ bias,
              float* __restrict__ C, int ldc)
{
    __shared__ float As[16][64];
    __shared__ float Ws[16][68];

    int tid = threadIdx.x;
    int tx = tid & 15, ty = tid >> 4;
    int bm = blockIdx.y * 64, bn = blockIdx.x * 64;
    int kb = blockIdx.z * Ks;
    int arow = tid >> 2, acol = (tid & 3) << 2;
    int wn = tx * 4;
    bool wok = (bn + wn) < N;

    const float* Arow = A + (size_t)(bm + arow) * lda + acol;
    float4 pa = *(const float4*)(Arow + kb);
    float4 pw = make_float4(0.f, 0.f, 0.f, 0.f);
    if (wok) pw = *(const float4*)(W + (size_t)(kb + ty) * N + bn + wn);

    float acc[4][4] = {};

    for (int k0 = kb; k0 < kb + Ks; k0 += 16) {
        __syncthreads();
        As[acol + 0][arow] = pa.x;
        As[acol + 1][arow] = pa.y;
        As[acol + 2][arow] = pa.z;
        As[acol + 3][arow] = pa.w;
        *(float4*)&Ws[ty][wn] = pw;
        __syncthreads();

        if (k0 + 16 < kb + Ks) {
            pa = *(const float4*)(Arow + k0 + 16);
            if (wok) pw = *(const float4*)(W + (size_t)(k0 + 16 + ty) * N + bn + wn);
        }

        #pragma unroll
        for (int k = 0; k < 16; k++) {
            float4 a0 = *(const float4*)&As[k][ty * 4];
            float4 w0 = *(const float4*)&Ws[k][tx * 4];
            float a[4] = {a0.x, a0.y, a0.z, a0.w};
            float w[4] = {w0.x, w0.y, w0.z, w0.w};
            #pragma unroll
            for (int i = 0; i < 4; i++)
                #pragma unroll
                for (int j = 0; j < 4; j++) acc[i][j] += a[i] * w[j];
        }
    }

    if (EPI == 2) {
        #pragma unroll
        for (int i = 0; i < 4; i++) {
            int row = bm + ty * 4 + i;
            #pragma unroll
            for (int j = 0; j < 4; j++) {
                int col = bn + tx * 4 + j;
                if (col < N) atomicAdd(&C[(size_t)row * ldc + col], acc[i][j]);
            }
        }
    } else {
        float rowsq[4];
        #pragma unroll
        for (int i = 0; i < 4; i++) {
            int row = bm + ty * 4 + i;
            float sq = 0.f;
            #pragma unroll
            for (int j = 0; j < 4; j++) {
                int col = bn + tx * 4 + j;
                float v = acc[i][j];
                if (EPI == 0) { if (bias) v += bias[col]; }
                else          { v += C[(size_t)row * ldc + col]; }
                C[(size_t)row * ldc + col] = v;
                sq += v * v;
            }
            rowsq[i] = sq;
        }
        #pragma unroll
        for (int o = 1; o < 16; o <<= 1)
            #pragma unroll
            for (int i = 0; i < 4; i++)
                rowsq[i] += __shfl_xor_sync(0xffffffffu, rowsq[i], o);
        if (tx == 0) {
            #pragma unroll
            for (int i = 0; i < 4; i++)
                atomicAdd(&g_rs2[bm + ty * 4 + i], rowsq[i]);
        }
    }
}

// ---------------- causal depthwise conv (k=4) + silu, float4; zero proj -------
__global__ void k_conv(const float* __restrict__ cw, const float* __restrict__ cb)
{
    int idx = blockIdx.x * blockDim.x + threadIdx.x;   // over MTOK * DI/4
    if (idx < MTOK * 48) g_proj[idx] = 0.f;            // zero proj for split-K
    if (idx >= MTOK * (DI / 4)) return;
    int m = idx / (DI / 4), dv = idx % (DI / 4);
    int d = dv * 4;
    int b = m / TSEQ, t = m % TSEQ;

    float4 acc = *(const float4*)(cb + d);
    #pragma unroll
    for (int k = 0; k < 4; k++) {
        int tt = t - 3 + k;
        if (tt >= 0) {
            float4 v = *(const float4*)(g_xz + (size_t)(b * TSEQ + tt) * (2 * DI) + d);
            acc.x += cw[(d + 0) * 4 + k] * v.x;
            acc.y += cw[(d + 1) * 4 + k] * v.y;
            acc.z += cw[(d + 2) * 4 + k] * v.z;
            acc.w += cw[(d + 3) * 4 + k] * v.w;
        }
    }
    acc.x = acc.x / (1.f + __expf(-acc.x));
    acc.y = acc.y / (1.f + __expf(-acc.y));
    acc.z = acc.z / (1.f + __expf(-acc.z));
    acc.w = acc.w / (1.f + __expf(-acc.w));
    *(float4*)(g_xc + (size_t)m * DI + d) = acc;
}

// ---------------- selective scan, 4-way state split, fused dt-GEMM -------------
// 128 blocks x 128 threads; thread = (b, d, 4-state slice); zeroes rs2 for out-GEMM.
__global__ __launch_bounds__(128)
void k_scan(const float* __restrict__ A_log, const float* __restrict__ Dp,
            const float* __restrict__ dtW, const float* __restrict__ dtb)
{
    int tid = threadIdx.x;
    int sub = tid & 3;                 // state slice 0..3
    int dloc = tid >> 2;               // 0..31
    int b = blockIdx.x >> 4;
    int d = ((blockIdx.x & 15) << 5) + dloc;

    int gid = blockIdx.x * 128 + tid;
    if (gid < MTOK) g_rs2[gid] = 0.f;  // zero sumsq for out-GEMM epilogue

    float A[4], h[4] = {};
    #pragma unroll
    for (int j = 0; j < 4; j++) A[j] = -__expf(A_log[d * DS + sub * 4 + j]);

    float W16[16];
    #pragma unroll
    for (int r = 0; r < 16; r++) W16[r] = dtW[r * DI + d];
    float bd = dtb[d], Dd = Dp[d];

    __shared__ float sp[8][48];

    for (int t0 = 0; t0 < TSEQ; t0 += 8) {
        __syncthreads();
        #pragma unroll
        for (int i = 0; i < 3; i++) {
            int idx = tid + i * 128;
            int st = idx / 48, j = idx % 48;
            sp[st][j] = g_proj[((size_t)(b * TSEQ + t0 + st)) * 48 + j];
        }
        __syncthreads();

        #pragma unroll
        for (int tt = 0; tt < 8; tt++) {
            int m = b * TSEQ + t0 + tt;
            float dtr = bd;
            #pragma unroll
            for (int r = 0; r < 16; r++) dtr += sp[tt][r] * W16[r];
            float dt = (dtr > 15.f) ? dtr : log1pf(__expf(dtr));
            float x = g_xc[(size_t)m * DI + d];
            float dtx = dt * x;
            float y = 0.f;
            #pragma unroll
            for (int j = 0; j < 4; j++) {
                int n = sub * 4 + j;
                float dA = __expf(dt * A[j]);
                h[j] = dA * h[j] + dtx * sp[tt][16 + n];
                y += h[j] * sp[tt][32 + n];
            }
            y += __shfl_xor_sync(0xffffffffu, y, 1);
            y += __shfl_xor_sync(0xffffffffu, y, 2);
            if (sub == 0) {
                float z = g_xz[(size_t)m * (2 * DI) + DI + d];
                float o = (y + x * Dd) * (z / (1.f + __expf(-z)));
                g_y[(size_t)m * DI + d] = o;
            }
        }
    }
}

// ---------------- heads with fused final rmsnorm ----------------
__global__ void k_heads(const float* __restrict__ fnw,
                        const float* __restrict__ ps_W, const float* __restrict__ ps_b,
                        const float* __restrict__ pa_W, const float* __restrict__ pa_b,
                        float* __restrict__ out)
{
    int idx = blockIdx.x * blockDim.x + threadIdx.x;
    if (idx >= 6144 + 3072) return;
    if (idx < 6144) {
        int j = idx % 6; int l = (idx / 6) % LQ; int b = idx / (6 * LQ);
        int m = b * TSEQ + l * 3 + 2;   // action-slot tokens -> state preds
        float scale = rsqrtf(g_rs2[m] * (1.f / DM) + 1e-5f);
        float acc = 0.f;
        const float* f = g_res + (size_t)m * DM;
        #pragma unroll 8
        for (int e = 0; e < DM; e++) acc += f[e] * fnw[e] * ps_W[e * 6 + j];
        out[idx] = acc * scale + ps_b[j];
    } else {
        int k = idx - 6144;
        int j = k % 3; int l = (k / 3) % LQ; int b = k / (3 * LQ);
        int m = b * TSEQ + l * 3 + 1;   // state-slot tokens -> action preds
        float scale = rsqrtf(g_rs2[m] * (1.f / DM) + 1e-5f);
        float acc = 0.f;
        const float* f = g_res + (size_t)m * DM;
        #pragma unroll 8
        for (int e = 0; e < DM; e++) acc += f[e] * fnw[e] * pa_W[e * 3 + j];
        out[idx] = tanhf(acc * scale + pa_b[j]);
    }
}

// ---------------- launch ----------------
extern "C" void kernel_launch(void* const* d_in, const int* in_sizes, int n_in,
                              void* d_out, int out_size)
{
    const float* states    = (const float*)d_in[0];
    const float* actions   = (const float*)d_in[1];
    const float* goal      = (const float*)d_in[2];
    const int*   timesteps = (const int*)  d_in[3];
    const float* te_W      = (const float*)d_in[4];
    const float* se_W      = (const float*)d_in[5];
    const float* se_b      = (const float*)d_in[6];
    const float* ge_W      = (const float*)d_in[7];
    const float* ge_b      = (const float*)d_in[8];
    const float* ae_W      = (const float*)d_in[9];
    const float* ae_b      = (const float*)d_in[10];
    const float* bb_in_W   = (const float*)d_in[11];
    const float* bb_in_b   = (const float*)d_in[12];
    const float* norm_w    = (const float*)d_in[13];
    const float* in_proj_W = (const float*)d_in[14];
    const float* conv_w    = (const float*)d_in[15];
    const float* conv_b    = (const float*)d_in[16];
    const float* xproj_W   = (const float*)d_in[17];
    const float* dt_W      = (const float*)d_in[18];
    const float* dt_b      = (const float*)d_in[19];
    const float* A_log     = (const float*)d_in[20];
    const float* Dp        = (const float*)d_in[21];
    const float* out_W     = (const float*)d_in[22];
    const float* fnorm_w   = (const float*)d_in[23];
    const float* ps_W      = (const float*)d_in[24];
    const float* ps_b      = (const float*)d_in[25];
    const float* pa_W      = (const float*)d_in[26];
    const float* pa_b      = (const float*)d_in[27];
    float* out = (float*)d_out;

    float *pu, *pres, *pxz, *pxc, *pproj, *py;
    cudaGetSymbolAddress((void**)&pu,    g_u);
    cudaGetSymbolAddress((void**)&pres,  g_res);
    cudaGetSymbolAddress((void**)&pxz,   g_xz);
    cudaGetSymbolAddress((void**)&pxc,   g_xc);
    cudaGetSymbolAddress((void**)&pproj, g_proj);
    cudaGetSymbolAddress((void**)&py,    g_y);

    // 1) embeddings -> u  (also zeroes rs2)
    k_embed<<<MTOK, DM>>>(states, actions, goal, timesteps, te_W,
                          se_W, se_b, ge_W, ge_b, ae_W, ae_b);

    // 2) residual = u @ bb_in_W + b ; rs2 += row sumsq
    k_gemm64<0><<<dim3(DM / 64, MTOK / 64, 1), 256>>>(
        pu, DM, bb_in_W, DM, DM, bb_in_b, pres, DM);

    // 3) mamba layers
    for (int i = 0; i < NL; i++) {
        const float* inW  = in_proj_W + (size_t)i * DM * 2 * DI;
        const float* cw   = conv_w    + (size_t)i * DI * 4;
        const float* cb   = conv_b    + (size_t)i * DI;
        const float* xpW  = xproj_W   + (size_t)i * DI * 48;
        const float* dtW  = dt_W      + (size_t)i * RK * DI;
        const float* dtb  = dt_b      + (size_t)i * DI;
        const float* Al   = A_log     + (size_t)i * DI * DS;
        const float* Dpi  = Dp        + (size_t)i * DI;
        const float* oW   = out_W     + (size_t)i * DI * DM;
        const float* nw   = norm_w    + (size_t)i * DM;

        // xz = rmsnorm(res; rs2, nw) @ in_W   (3072 x 1024 x 256)
        k_inproj<<<dim3(1024 / 64, MTOK / 128), 256>>>(pres, inW, nw, pxz);

        // causal depthwise conv + silu -> xc ; zero proj
        k_conv<<<(MTOK * DI / 4 + 255) / 256, 256>>>(cw, cb);

        // proj = xc @ xproj_W  (3072 x 48 x 512), split-K x4, atomic accumulate
        k_gemm64<2><<<dim3(1, MTOK / 64, 4), 256>>>(
            pxc, DI, xpW, 48, DI / 4, nullptr, pproj, 48);

        // selective scan (fused dt-GEMM + softplus + gate) -> y ; zero rs2
        k_scan<<<128, 128>>>(Al, Dpi, dtW, dtb);

        // residual += y @ out_W ; rs2 += row sumsq
        k_gemm64<1><<<dim3(DM / 64, MTOK / 64, 1), 256>>>(
            py, DI, oW, DM, DI, nullptr, pres, DM);
    }

    // 4) heads (fused final rmsnorm)
    k_heads<<<(9216 + 255) / 256, 256>>>(fnorm_w, ps_W, ps_b, pa_W, pa_b, out);
}

// round 4
// speedup vs baseline: 1.0249x; 1.0249x over previous
#include <cuda_runtime.h>
#include <math.h>

// ---------------- problem constants ----------------
#define BQ   8
#define LQ   128
#define TSEQ 384          // 3 * L tokens per batch
#define MTOK 3072         // BQ * TSEQ
#define DM   256          // d_model
#define DI   512          // d_inner
#define DS   16           // d_state
#define RK   16           // dt_rank
#define NL   4

// ---------------- scratch ----------------
__device__ float g_u   [MTOK * DM];
__device__ float g_res [MTOK * DM];
__device__ float g_rs2 [MTOK];          // per-row sum of squares (for rmsnorm)
__device__ float g_xz  [MTOK * 2 * DI];
__device__ float g_xc  [MTOK * DI];
__device__ float g_proj[MTOK * 48];
__device__ float g_y   [MTOK * DI];

// ---------------- packed f32x2 helpers (sm_103a FFMA2 path) ----------------
__device__ __forceinline__ unsigned long long pack2(float lo, float hi) {
    unsigned long long r;
    asm("mov.b64 %0, {%1, %2};" : "=l"(r) : "r"(__float_as_uint(lo)), "r"(__float_as_uint(hi)));
    return r;
}
__device__ __forceinline__ void fma2(unsigned long long& d,
                                     unsigned long long a, unsigned long long b) {
    asm("fma.rn.f32x2 %0, %1, %2, %0;" : "+l"(d) : "l"(a), "l"(b));
}
__device__ __forceinline__ float2 unpack2(unsigned long long v) {
    unsigned int lo, hi;
    asm("mov.b64 {%0, %1}, %2;" : "=r"(lo), "=r"(hi) : "l"(v));
    return make_float2(__uint_as_float(lo), __uint_as_float(hi));
}

// ---------------- embeddings + interleave -> u ; zero rs2 ----------------
__global__ void k_embed(const float* __restrict__ states,
                        const float* __restrict__ actions,
                        const float* __restrict__ goal,
                        const int*   __restrict__ timesteps,
                        const float* __restrict__ te_W,
                        const float* __restrict__ se_W, const float* __restrict__ se_b,
                        const float* __restrict__ ge_W, const float* __restrict__ ge_b,
                        const float* __restrict__ ae_W, const float* __restrict__ ae_b)
{
    int m = blockIdx.x;          // token 0..3071
    int e = threadIdx.x;         // 0..255
    if (e == 0) g_rs2[m] = 0.f;  // zero sumsq for bb_in epilogue
    int b = m / TSEQ, t = m % TSEQ;
    int slot = t % 3, l = t / 3;

    const float *inp, *Wm, *bi; int dim;
    if (slot == 0)      { inp = goal;    Wm = ge_W; bi = ge_b; dim = 6; }
    else if (slot == 1) { inp = states;  Wm = se_W; bi = se_b; dim = 6; }
    else                { inp = actions; Wm = ae_W; bi = ae_b; dim = 3; }

    float v = bi[e];
    const float* ip = inp + (size_t)(b * LQ + l) * dim;
    #pragma unroll 6
    for (int i = 0; i < dim; i++) v += ip[i] * Wm[i * DM + e];

    int ts = timesteps[b * LQ + l];
    v += te_W[(size_t)ts * DM + e];
    g_u[(size_t)m * DM + e] = v;
}

// ---------------- 128x64 prefetched SGEMM, 8x4/thread, FFMA2 inner loop -------
// EPI 0: C = acc (+bias), atomic row-sumsq into g_rs2          (bb_in)
// EPI 1: C += acc,        atomic row-sumsq into g_rs2          (out_proj)
// EPI 2: C = acc                                                (in_proj)
// NORM: A-load multiplied by rsqrt(g_rs2[row]/DM+eps) * nw[k]   (in_proj)
// Requires: M%128==0, N%64==0, K%16==0.
template<int EPI, bool NORM>
__global__ __launch_bounds__(256)
void k_gemm128(const float* __restrict__ A, int lda,
               const float* __restrict__ W, int N, int K,
               const float* __restrict__ bias,
               const float* __restrict__ nw,
               float* __restrict__ C, int ldc)
{
    __shared__ float As[16][128];
    __shared__ float Ws[16][68];

    int tid = threadIdx.x;
    int bm = blockIdx.y * 128, bn = blockIdx.x * 64;
    int tx = tid & 15;        // col group (4 cols)
    int ty = tid >> 4;        // row group (8 rows)
    int arow = tid >> 2;      // 0..63
    int acol = (tid & 3) * 4; // 0,4,8,12
    int wn = tx * 4;          // W col within tile; k-row = ty

    float s0 = 1.f, s1 = 1.f;
    if (NORM) {
        s0 = rsqrtf(g_rs2[bm + arow]      * (1.f / DM) + 1e-5f);
        s1 = rsqrtf(g_rs2[bm + arow + 64] * (1.f / DM) + 1e-5f);
    }

    const float* Ap0 = A + (size_t)(bm + arow) * lda + acol;
    const float* Ap1 = Ap0 + (size_t)64 * lda;

    float4 pa0 = *(const float4*)(Ap0);
    float4 pa1 = *(const float4*)(Ap1);
    float4 pw  = *(const float4*)(W + (size_t)ty * N + bn + wn);

    unsigned long long acc2[8][2];
    #pragma unroll
    for (int i = 0; i < 8; i++) { acc2[i][0] = 0ull; acc2[i][1] = 0ull; }

    for (int k0 = 0; k0 < K; k0 += 16) {
        __syncthreads();
        if (NORM) {
            float n0 = nw[k0 + acol + 0], n1 = nw[k0 + acol + 1];
            float n2 = nw[k0 + acol + 2], n3 = nw[k0 + acol + 3];
            As[acol + 0][arow] = pa0.x * s0 * n0;
            As[acol + 1][arow] = pa0.y * s0 * n1;
            As[acol + 2][arow] = pa0.z * s0 * n2;
            As[acol + 3][arow] = pa0.w * s0 * n3;
            As[acol + 0][arow + 64] = pa1.x * s1 * n0;
            As[acol + 1][arow + 64] = pa1.y * s1 * n1;
            As[acol + 2][arow + 64] = pa1.z * s1 * n2;
            As[acol + 3][arow + 64] = pa1.w * s1 * n3;
        } else {
            As[acol + 0][arow] = pa0.x;
            As[acol + 1][arow] = pa0.y;
            As[acol + 2][arow] = pa0.z;
            As[acol + 3][arow] = pa0.w;
            As[acol + 0][arow + 64] = pa1.x;
            As[acol + 1][arow + 64] = pa1.y;
            As[acol + 2][arow + 64] = pa1.z;
            As[acol + 3][arow + 64] = pa1.w;
        }
        *(float4*)&Ws[ty][wn] = pw;
        __syncthreads();

        if (k0 + 16 < K) {
            pa0 = *(const float4*)(Ap0 + k0 + 16);
            pa1 = *(const float4*)(Ap1 + k0 + 16);
            pw  = *(const float4*)(W + (size_t)(k0 + 16 + ty) * N + bn + wn);
        }

        #pragma unroll
        for (int k = 0; k < 16; k++) {
            float4 a0 = *(const float4*)&As[k][ty * 8];
            float4 a1 = *(const float4*)&As[k][ty * 8 + 4];
            float4 w0 = *(const float4*)&Ws[k][tx * 4];
            unsigned long long w01 = pack2(w0.x, w0.y);
            unsigned long long w23 = pack2(w0.z, w0.w);
            float a[8] = {a0.x, a0.y, a0.z, a0.w, a1.x, a1.y, a1.z, a1.w};
            #pragma unroll
            for (int i = 0; i < 8; i++) {
                unsigned long long aa = pack2(a[i], a[i]);
                fma2(acc2[i][0], aa, w01);
                fma2(acc2[i][1], aa, w23);
            }
        }
    }

    if (EPI == 2) {
        #pragma unroll
        for (int i = 0; i < 8; i++) {
            int row = bm + ty * 8 + i;
            float2 v01 = unpack2(acc2[i][0]);
            float2 v23 = unpack2(acc2[i][1]);
            *(float4*)&C[(size_t)row * ldc + bn + tx * 4] =
                make_float4(v01.x, v01.y, v23.x, v23.y);
        }
    } else {
        float rowsq[8];
        #pragma unroll
        for (int i = 0; i < 8; i++) {
            int row = bm + ty * 8 + i;
            float2 v01 = unpack2(acc2[i][0]);
            float2 v23 = unpack2(acc2[i][1]);
            float v[4] = {v01.x, v01.y, v23.x, v23.y};
            float sq = 0.f;
            #pragma unroll
            for (int j = 0; j < 4; j++) {
                int col = bn + tx * 4 + j;
                float val = v[j];
                if (EPI == 0) { if (bias) val += bias[col]; }
                else          { val += C[(size_t)row * ldc + col]; }
                C[(size_t)row * ldc + col] = val;
                sq += val * val;
            }
            rowsq[i] = sq;
        }
        #pragma unroll
        for (int o = 1; o < 16; o <<= 1)
            #pragma unroll
            for (int i = 0; i < 8; i++)
                rowsq[i] += __shfl_xor_sync(0xffffffffu, rowsq[i], o);
        if (tx == 0) {
            #pragma unroll
            for (int i = 0; i < 8; i++)
                atomicAdd(&g_rs2[bm + ty * 8 + i], rowsq[i]);
        }
    }
}

// ---------------- 64x64 split-K SGEMM (xproj, N=48), FFMA2, atomic epilogue ----
__global__ __launch_bounds__(256)
void k_xproj(const float* __restrict__ A, int lda,
             const float* __restrict__ W, int N, int Ks,
             float* __restrict__ C, int ldc)
{
    __shared__ float As[16][64];
    __shared__ float Ws[16][68];

    int tid = threadIdx.x;
    int tx = tid & 15, ty = tid >> 4;
    int bm = blockIdx.y * 64, bn = blockIdx.x * 64;
    int kb = blockIdx.z * Ks;
    int arow = tid >> 2, acol = (tid & 3) << 2;
    int wn = tx * 4;
    bool wok = (bn + wn) < N;

    const float* Arow = A + (size_t)(bm + arow) * lda + acol;
    float4 pa = *(const float4*)(Arow + kb);
    float4 pw = make_float4(0.f, 0.f, 0.f, 0.f);
    if (wok) pw = *(const float4*)(W + (size_t)(kb + ty) * N + bn + wn);

    unsigned long long acc2[4][2];
    #pragma unroll
    for (int i = 0; i < 4; i++) { acc2[i][0] = 0ull; acc2[i][1] = 0ull; }

    for (int k0 = kb; k0 < kb + Ks; k0 += 16) {
        __syncthreads();
        As[acol + 0][arow] = pa.x;
        As[acol + 1][arow] = pa.y;
        As[acol + 2][arow] = pa.z;
        As[acol + 3][arow] = pa.w;
        *(float4*)&Ws[ty][wn] = pw;
        __syncthreads();

        if (k0 + 16 < kb + Ks) {
            pa = *(const float4*)(Arow + k0 + 16);
            if (wok) pw = *(const float4*)(W + (size_t)(k0 + 16 + ty) * N + bn + wn);
        }

        #pragma unroll
        for (int k = 0; k < 16; k++) {
            float4 a0 = *(const float4*)&As[k][ty * 4];
            float4 w0 = *(const float4*)&Ws[k][tx * 4];
            unsigned long long w01 = pack2(w0.x, w0.y);
            unsigned long long w23 = pack2(w0.z, w0.w);
            float a[4] = {a0.x, a0.y, a0.z, a0.w};
            #pragma unroll
            for (int i = 0; i < 4; i++) {
                unsigned long long aa = pack2(a[i], a[i]);
                fma2(acc2[i][0], aa, w01);
                fma2(acc2[i][1], aa, w23);
            }
        }
    }

    #pragma unroll
    for (int i = 0; i < 4; i++) {
        int row = bm + ty * 4 + i;
        float2 v01 = unpack2(acc2[i][0]);
        float2 v23 = unpack2(acc2[i][1]);
        float v[4] = {v01.x, v01.y, v23.x, v23.y};
        #pragma unroll
        for (int j = 0; j < 4; j++) {
            int col = bn + tx * 4 + j;
            if (col < N) atomicAdd(&C[(size_t)row * ldc + col], v[j]);
        }
    }
}

// ---------------- causal depthwise conv (k=4) + silu, 4 tokens/thread ----------
// Also zeroes g_proj for the split-K xproj that follows.
__global__ void k_conv(const float* __restrict__ cw, const float* __restrict__ cb)
{
    int idx = blockIdx.x * blockDim.x + threadIdx.x;  // over (MTOK/4)*(DI/4)=98304
    {
        if (idx < MTOK * 48) g_proj[idx] = 0.f;
        int i2 = idx + 98304;
        if (i2 < MTOK * 48) g_proj[i2] = 0.f;
    }
    if (idx >= (MTOK / 4) * (DI / 4)) return;
    int mg = idx / (DI / 4), dv = idx % (DI / 4);
    int d = dv * 4;
    int b = mg / (TSEQ / 4), tg = mg % (TSEQ / 4);
    int t0 = tg * 4;

    float4 win[7];
    #pragma unroll
    for (int j = 0; j < 7; j++) {
        int tt = t0 - 3 + j;
        win[j] = (tt >= 0)
            ? *(const float4*)(g_xz + (size_t)(b * TSEQ + tt) * (2 * DI) + d)
            : make_float4(0.f, 0.f, 0.f, 0.f);
    }

    float4 cw0 = *(const float4*)(cw + (d + 0) * 4);
    float4 cw1 = *(const float4*)(cw + (d + 1) * 4);
    float4 cw2 = *(const float4*)(cw + (d + 2) * 4);
    float4 cw3 = *(const float4*)(cw + (d + 3) * 4);
    float4 cb4 = *(const float4*)(cb + d);

    #pragma unroll
    for (int j2 = 0; j2 < 4; j2++) {
        float4 acc = cb4;
        float cwk[4][4] = {{cw0.x, cw0.y, cw0.z, cw0.w},
                           {cw1.x, cw1.y, cw1.z, cw1.w},
                           {cw2.x, cw2.y, cw2.z, cw2.w},
                           {cw3.x, cw3.y, cw3.z, cw3.w}};
        #pragma unroll
        for (int k = 0; k < 4; k++) {
            float4 v = win[j2 + k];
            acc.x += cwk[0][k] * v.x;
            acc.y += cwk[1][k] * v.y;
            acc.z += cwk[2][k] * v.z;
            acc.w += cwk[3][k] * v.w;
        }
        acc.x = acc.x / (1.f + __expf(-acc.x));
        acc.y = acc.y / (1.f + __expf(-acc.y));
        acc.z = acc.z / (1.f + __expf(-acc.z));
        acc.w = acc.w / (1.f + __expf(-acc.w));
        *(float4*)(g_xc + (size_t)(b * TSEQ + t0 + j2) * DI + d) = acc;
    }
}

// ---------------- selective scan, 4-way state split, fused dt-GEMM -------------
__global__ __launch_bounds__(128)
void k_scan(const float* __restrict__ A_log, const float* __restrict__ Dp,
            const float* __restrict__ dtW, const float* __restrict__ dtb)
{
    int tid = threadIdx.x;
    int sub = tid & 3;                 // state slice 0..3
    int dloc = tid >> 2;               // 0..31
    int b = blockIdx.x >> 4;
    int d = ((blockIdx.x & 15) << 5) + dloc;

    int gid = blockIdx.x * 128 + tid;
    if (gid < MTOK) g_rs2[gid] = 0.f;  // zero sumsq for out-GEMM epilogue

    float A[4], h[4] = {};
    #pragma unroll
    for (int j = 0; j < 4; j++) A[j] = -__expf(A_log[d * DS + sub * 4 + j]);

    float W16[16];
    #pragma unroll
    for (int r = 0; r < 16; r++) W16[r] = dtW[r * DI + d];
    float bd = dtb[d], Dd = Dp[d];

    __shared__ float sp[8][48];

    for (int t0 = 0; t0 < TSEQ; t0 += 8) {
        __syncthreads();
        #pragma unroll
        for (int i = 0; i < 3; i++) {
            int idx = tid + i * 128;
            int st = idx / 48, j = idx % 48;
            sp[st][j] = g_proj[((size_t)(b * TSEQ + t0 + st)) * 48 + j];
        }
        __syncthreads();

        #pragma unroll
        for (int tt = 0; tt < 8; tt++) {
            int m = b * TSEQ + t0 + tt;
            float dtr = bd;
            #pragma unroll
            for (int r = 0; r < 16; r++) dtr += sp[tt][r] * W16[r];
            float dt = (dtr > 15.f) ? dtr : log1pf(__expf(dtr));
            float x = g_xc[(size_t)m * DI + d];
            float dtx = dt * x;
            float y = 0.f;
            #pragma unroll
            for (int j = 0; j < 4; j++) {
                int n = sub * 4 + j;
                float dA = __expf(dt * A[j]);
                h[j] = dA * h[j] + dtx * sp[tt][16 + n];
                y += h[j] * sp[tt][32 + n];
            }
            y += __shfl_xor_sync(0xffffffffu, y, 1);
            y += __shfl_xor_sync(0xffffffffu, y, 2);
            if (sub == 0) {
                float z = g_xz[(size_t)m * (2 * DI) + DI + d];
                float o = (y + x * Dd) * (z / (1.f + __expf(-z)));
                g_y[(size_t)m * DI + d] = o;
            }
        }
    }
}

// ---------------- heads with fused final rmsnorm ----------------
__global__ void k_heads(const float* __restrict__ fnw,
                        const float* __restrict__ ps_W, const float* __restrict__ ps_b,
                        const float* __restrict__ pa_W, const float* __restrict__ pa_b,
                        float* __restrict__ out)
{
    int idx = blockIdx.x * blockDim.x + threadIdx.x;
    if (idx >= 6144 + 3072) return;
    if (idx < 6144) {
        int j = idx % 6; int l = (idx / 6) % LQ; int b = idx / (6 * LQ);
        int m = b * TSEQ + l * 3 + 2;   // action-slot tokens -> state preds
        float scale = rsqrtf(g_rs2[m] * (1.f / DM) + 1e-5f);
        float acc = 0.f;
        const float* f = g_res + (size_t)m * DM;
        #pragma unroll 8
        for (int e = 0; e < DM; e++) acc += f[e] * fnw[e] * ps_W[e * 6 + j];
        out[idx] = acc * scale + ps_b[j];
    } else {
        int k = idx - 6144;
        int j = k % 3; int l = (k / 3) % LQ; int b = k / (3 * LQ);
        int m = b * TSEQ + l * 3 + 1;   // state-slot tokens -> action preds
        float scale = rsqrtf(g_rs2[m] * (1.f / DM) + 1e-5f);
        float acc = 0.f;
        const float* f = g_res + (size_t)m * DM;
        #pragma unroll 8
        for (int e = 0; e < DM; e++) acc += f[e] * fnw[e] * pa_W[e * 3 + j];
        out[idx] = tanhf(acc * scale + pa_b[j]);
    }
}

// ---------------- launch ----------------
extern "C" void kernel_launch(void* const* d_in, const int* in_sizes, int n_in,
                              void* d_out, int out_size)
{
    const float* states    = (const float*)d_in[0];
    const float* actions   = (const float*)d_in[1];
    const float* goal      = (const float*)d_in[2];
    const int*   timesteps = (const int*)  d_in[3];
    const float* te_W      = (const float*)d_in[4];
    const float* se_W      = (const float*)d_in[5];
    const float* se_b      = (const float*)d_in[6];
    const float* ge_W      = (const float*)d_in[7];
    const float* ge_b      = (const float*)d_in[8];
    const float* ae_W      = (const float*)d_in[9];
    const float* ae_b      = (const float*)d_in[10];
    const float* bb_in_W   = (const float*)d_in[11];
    const float* bb_in_b   = (const float*)d_in[12];
    const float* norm_w    = (const float*)d_in[13];
    const float* in_proj_W = (const float*)d_in[14];
    const float* conv_w    = (const float*)d_in[15];
    const float* conv_b    = (const float*)d_in[16];
    const float* xproj_W   = (const float*)d_in[17];
    const float* dt_W      = (const float*)d_in[18];
    const float* dt_b      = (const float*)d_in[19];
    const float* A_log     = (const float*)d_in[20];
    const float* Dp        = (const float*)d_in[21];
    const float* out_W     = (const float*)d_in[22];
    const float* fnorm_w   = (const float*)d_in[23];
    const float* ps_W      = (const float*)d_in[24];
    const float* ps_b      = (const float*)d_in[25];
    const float* pa_W      = (const float*)d_in[26];
    const float* pa_b      = (const float*)d_in[27];
    float* out = (float*)d_out;

    float *pu, *pres, *pxz, *pxc, *pproj, *py;
    cudaGetSymbolAddress((void**)&pu,    g_u);
    cudaGetSymbolAddress((void**)&pres,  g_res);
    cudaGetSymbolAddress((void**)&pxz,   g_xz);
    cudaGetSymbolAddress((void**)&pxc,   g_xc);
    cudaGetSymbolAddress((void**)&pproj, g_proj);
    cudaGetSymbolAddress((void**)&py,    g_y);

    // 1) embeddings -> u  (also zeroes rs2)
    k_embed<<<MTOK, DM>>>(states, actions, goal, timesteps, te_W,
                          se_W, se_b, ge_W, ge_b, ae_W, ae_b);

    // 2) residual = u @ bb_in_W + b ; rs2 += row sumsq
    k_gemm128<0, false><<<dim3(DM / 64, MTOK / 128), 256>>>(
        pu, DM, bb_in_W, DM, DM, bb_in_b, nullptr, pres, DM);

    // 3) mamba layers
    for (int i = 0; i < NL; i++) {
        const float* inW  = in_proj_W + (size_t)i * DM * 2 * DI;
        const float* cw   = conv_w    + (size_t)i * DI * 4;
        const float* cb   = conv_b    + (size_t)i * DI;
        const float* xpW  = xproj_W   + (size_t)i * DI * 48;
        const float* dtW  = dt_W      + (size_t)i * RK * DI;
        const float* dtb  = dt_b      + (size_t)i * DI;
        const float* Al   = A_log     + (size_t)i * DI * DS;
        const float* Dpi  = Dp        + (size_t)i * DI;
        const float* oW   = out_W     + (size_t)i * DI * DM;
        const float* nw   = norm_w    + (size_t)i * DM;

        // xz = rmsnorm(res; rs2, nw) @ in_W   (3072 x 1024 x 256)
        k_gemm128<2, true><<<dim3(1024 / 64, MTOK / 128), 256>>>(
            pres, DM, inW, 2 * DI, DM, nullptr, nw, pxz, 2 * DI);

        // causal depthwise conv + silu -> xc ; zero proj
        k_conv<<<((MTOK / 4) * (DI / 4)) / 256, 256>>>(cw, cb);

        // proj = xc @ xproj_W  (3072 x 48 x 512), split-K x4, atomic accumulate
        k_xproj<<<dim3(1, MTOK / 64, 4), 256>>>(pxc, DI, xpW, 48, DI / 4, pproj, 48);

        // selective scan (fused dt-GEMM + softplus + gate) -> y ; zero rs2
        k_scan<<<128, 128>>>(Al, Dpi, dtW, dtb);

        // residual += y @ out_W ; rs2 += row sumsq   (3072 x 256 x 512)
        k_gemm128<1, false><<<dim3(DM / 64, MTOK / 128), 256>>>(
            py, DI, oW, DM, DI, nullptr, nullptr, pres, DM);
    }

    // 4) heads (fused final rmsnorm)
    k_heads<<<(9216 + 255) / 256, 256>>>(fnorm_w, ps_W, ps_b, pa_W, pa_b, out);
}